// round 16
// baseline (speedup 1.0000x reference)
#include <cuda_runtime.h>
#include <cstdint>

#define BH   32
#define LSEQ 4096
#define DK   16
#define DV   64
#define CS   256
#define NC   16

// Symmetric-pair state: 136 pair rows (d<=e) + 16 linear rows + 1 ones row,
// padded to 160 rows x 72 cols (64 v-cols + 1 aux-sum col + 7 zero pads).
#define NP   160
#define NW   72
#define ST_STRIDE (NP * NW)   // 11520

#define SKB_STRIDE 264        // k_build k layout stride (== 8 mod 32)
#define SV2_STRIDE 132        // packed-pair B tiles stride (== 4 mod 32)

__device__ float g_state[(size_t)BH * NC * ST_STRIDE];

__device__ __forceinline__ unsigned f2t(float x) {
    unsigned u;
    asm("cvt.rna.tf32.f32 %0, %1;" : "=r"(u) : "f"(x));
    return u;
}
__device__ __forceinline__ float f2tf(float x) { return __uint_as_float(f2t(x)); }

// pack two fp32 -> fp16x2 (lo in low half)
__device__ __forceinline__ unsigned pack2(float lo, float hi) {
    unsigned r;
    asm("cvt.rn.f16x2.f32 %0, %1, %2;" : "=r"(r) : "f"(hi), "f"(lo));
    return r;
}

__device__ __forceinline__ void mma16(float* c, unsigned a0, unsigned a1,
                                      unsigned a2, unsigned a3,
                                      unsigned b0, unsigned b1) {
    asm volatile(
        "mma.sync.aligned.m16n8k16.row.col.f32.f16.f16.f32 "
        "{%0,%1,%2,%3},{%4,%5,%6,%7},{%8,%9},{%0,%1,%2,%3};"
        : "+f"(c[0]), "+f"(c[1]), "+f"(c[2]), "+f"(c[3])
        : "r"(a0), "r"(a1), "r"(a2), "r"(a3), "r"(b0), "r"(b1));
}

// p -> (d, e, w). d,e in [0,16]; index 16 hits the pad slot (=1.0f).
// spde packs (2d | 2e<<8) for the z-scalar loop over the sqp layout.
__device__ __forceinline__ void lut_build(int* spd, int* spe, float* sw,
                                          int* spde, int tid) {
    if (tid < NP) {
        int p = tid, d = 0, e;
        float w;
        if (p < 136) {
            int base = 0;
            while (base + (16 - d) <= p) { base += 16 - d; d++; }
            e = d + (p - base);
            w = (d == e) ? 0.5f : 1.0f;
        } else if (p < 152) { d = p - 136; e = 16; w = 1.f; }
        else if (p == 152) { d = 16; e = 16; w = 1.f; }
        else               { d = 16; e = 16; w = 0.f; }
        spd[p] = d; spe[p] = e; sw[p] = w;
        spde[p] = (2 * d) | ((2 * e) << 8);
    }
}

// ---------------------------------------------------------------------------
// Kernel 1: state build = single GEMM  st[160x72] = A[160x256] @ B[256x72]
// fp16 m16n8k16; A built in registers from skb (fp32, c-adjacent pairs);
// B = V+aux staged as fp16x2 pairs over adjacent c. 480 threads, 2 CTAs/SM.
// (Unchanged from the 123.4us baseline.)
// ---------------------------------------------------------------------------
__global__ __launch_bounds__(480, 2)
void k_build(const float* __restrict__ kin, const float* __restrict__ vin) {
    const int head = blockIdx.x, ch = blockIdx.y;
    extern __shared__ float sm[];
    float* skb = sm;                         // [17][SKB_STRIDE] fp32 k (+ones)
    unsigned* sBu = (unsigned*)(skb + 17 * SKB_STRIDE);  // [72][SV2_STRIDE]
    int*   spd = (int*)(sBu + NW * SV2_STRIDE);
    int*   spe = spd + NP;
    float* sw  = (float*)(spe + NP);
    int*   spde = (int*)(sw + NP);

    const float* kg = kin + ((size_t)head * LSEQ + (size_t)ch * CS) * DK;
    const float* vg = vin + ((size_t)head * LSEQ + (size_t)ch * CS) * DV;
    float* st = g_state + (size_t)(head * NC + ch) * ST_STRIDE;

    const int tid = threadIdx.x, warp = tid >> 5, lane = tid & 31;
    const int wm = warp / 3, wn = warp % 3, g = lane >> 2, tg = lane & 3;
    const int rb = 32 * wm, cb = 24 * wn;

    // stage k: skb[idx][c] fp32, idx 16 = ones
    for (int i = tid; i < CS * DK; i += 480) {
        int cc = i >> 4, idx = i & 15;
        skb[idx * SKB_STRIDE + cc] = kg[i];
    }
    for (int i = tid; i < CS; i += 480) skb[16 * SKB_STRIDE + i] = 1.0f;
    // stage B: half2 pairs over (c=2cp, 2cp+1); cols 0..63 = V, 64 = ones
    for (int i = tid; i < 128 * 18; i += 480) {
        int cp = i / 18, fg = i - cp * 18, f4 = fg * 4;
        if (f4 < 64) {
            float4 x0 = *(const float4*)&vg[(2 * cp) * 64 + f4];
            float4 x1 = *(const float4*)&vg[(2 * cp + 1) * 64 + f4];
            sBu[(f4 + 0) * SV2_STRIDE + cp] = pack2(x0.x, x1.x);
            sBu[(f4 + 1) * SV2_STRIDE + cp] = pack2(x0.y, x1.y);
            sBu[(f4 + 2) * SV2_STRIDE + cp] = pack2(x0.z, x1.z);
            sBu[(f4 + 3) * SV2_STRIDE + cp] = pack2(x0.w, x1.w);
        } else {
            #pragma unroll
            for (int u = 0; u < 4; u++) {
                int f = f4 + u;
                sBu[f * SV2_STRIDE + cp] = (f == 64) ? 0x3C003C00u : 0u;
            }
        }
    }
    lut_build(spd, spe, sw, spde, tid);
    __syncthreads();

    int rd[2][2], re[2][2];
    #pragma unroll
    for (int mt = 0; mt < 2; mt++) {
        int r0 = rb + 16 * mt + g;
        rd[mt][0] = spd[r0];     re[mt][0] = spe[r0];
        rd[mt][1] = spd[r0 + 8]; re[mt][1] = spe[r0 + 8];
    }

    float c[2][3][4];
    #pragma unroll
    for (int mt = 0; mt < 2; mt++)
        #pragma unroll
        for (int nt = 0; nt < 3; nt++)
            #pragma unroll
            for (int u = 0; u < 4; u++) c[mt][nt][u] = 0.f;

    #pragma unroll 4
    for (int ks = 0; ks < 16; ks++) {
        const int c0 = 16 * ks + 2 * tg;
        unsigned a[2][4];
        #pragma unroll
        for (int mt = 0; mt < 2; mt++) {
            float2 pd0 = *(float2*)&skb[rd[mt][0] * SKB_STRIDE + c0];
            float2 pe0 = *(float2*)&skb[re[mt][0] * SKB_STRIDE + c0];
            float2 pd1 = *(float2*)&skb[rd[mt][1] * SKB_STRIDE + c0];
            float2 pe1 = *(float2*)&skb[re[mt][1] * SKB_STRIDE + c0];
            a[mt][0] = pack2(pd0.x * pe0.x, pd0.y * pe0.y);  // row r0, c0..c0+1
            a[mt][1] = pack2(pd1.x * pe1.x, pd1.y * pe1.y);  // row r0+8
            float2 qd0 = *(float2*)&skb[rd[mt][0] * SKB_STRIDE + c0 + 8];
            float2 qe0 = *(float2*)&skb[re[mt][0] * SKB_STRIDE + c0 + 8];
            float2 qd1 = *(float2*)&skb[rd[mt][1] * SKB_STRIDE + c0 + 8];
            float2 qe1 = *(float2*)&skb[re[mt][1] * SKB_STRIDE + c0 + 8];
            a[mt][2] = pack2(qd0.x * qe0.x, qd0.y * qe0.y);  // row r0, c0+8..9
            a[mt][3] = pack2(qd1.x * qe1.x, qd1.y * qe1.y);
        }
        #pragma unroll
        for (int nt = 0; nt < 3; nt++) {
            int fc = cb + 8 * nt + g;
            unsigned b0 = sBu[fc * SV2_STRIDE + 8 * ks + tg];
            unsigned b1 = sBu[fc * SV2_STRIDE + 8 * ks + tg + 4];
            #pragma unroll
            for (int mt = 0; mt < 2; mt++)
                mma16(c[mt][nt], a[mt][0], a[mt][1], a[mt][2], a[mt][3],
                      b0, b1);
        }
    }

    #pragma unroll
    for (int mt = 0; mt < 2; mt++)
        #pragma unroll
        for (int nt = 0; nt < 3; nt++) {
            int r0 = rb + 16 * mt + g, col = cb + 8 * nt + 2 * tg;
            *(float2*)&st[r0 * NW + col] =
                make_float2(c[mt][nt][0], c[mt][nt][1]);
            *(float2*)&st[(r0 + 8) * NW + col] =
                make_float2(c[mt][nt][2], c[mt][nt][3]);
        }
}

// ---------------------------------------------------------------------------
// Kernel 2: exclusive prefix scan over chunk axis. One element per thread.
// ---------------------------------------------------------------------------
__global__ void k_scan() {
    float* base = g_state + (size_t)blockIdx.x * NC * ST_STRIDE +
                  blockIdx.y * blockDim.x + threadIdx.x;
    float v[NC];
    #pragma unroll
    for (int c = 0; c < NC; c++) v[c] = base[(size_t)c * ST_STRIDE];
    float run = 0.f;
    #pragma unroll
    for (int c = 0; c < NC; c++) {
        float t = v[c];
        v[c] = run;
        run += t;
    }
    #pragma unroll
    for (int c = 0; c < NC; c++) base[(size_t)c * ST_STRIDE] = v[c];
}

// ---------------------------------------------------------------------------
// Kernel 3: output. 512 threads, 2 CTAs/SM. Mirrored row tiles.
// fp16 m16n8k16. Intra phase SOFTWARE-PIPELINED: each iteration consumes the
// sf S-fragments into phi/af, immediately re-issues the NEXT step's S-mmas
// into the same (dead) sf registers, then runs the AV-mmas — hiding S-mma
// latency behind AV work with zero extra register pressure.
// ---------------------------------------------------------------------------
__global__ __launch_bounds__(512, 2)
void k_main(const float* __restrict__ qin, const float* __restrict__ kin,
            const float* __restrict__ vin, float* __restrict__ out) {
    const int head = blockIdx.x, ch = blockIdx.y;
    extern __shared__ float sm[];
    float* sqp = sm;                           // [128][34] fp32 q (row pairs)
    unsigned* sk2 = (unsigned*)(sqp + 128 * 34);      // [256][8] fp16x2 k
    unsigned* sv2 = sk2 + 256 * 8;                    // [64][SV2_STRIDE]
    float* szs = (float*)(sv2 + 64 * SV2_STRIDE);     // [256]
    int*   spd = (int*)(szs + 256);
    int*   spe = spd + NP;
    float* sw  = (float*)(spe + NP);
    int*   spde = (int*)(sw + NP);
    float* swst = (float*)(spde + NP);         // [160] w*state[:,64]

    const float* qg = qin + ((size_t)head * LSEQ + (size_t)ch * CS) * DK;
    const float* kg = kin + ((size_t)head * LSEQ + (size_t)ch * CS) * DK;
    const float* vg = vin + ((size_t)head * LSEQ + (size_t)ch * CS) * DV;
    const float* st = g_state + (size_t)(head * NC + ch) * ST_STRIDE;

    const int tid = threadIdx.x, warp = tid >> 5, lane = tid & 31;
    const int wm = warp >> 1, wn = warp & 1, g = lane >> 2, tg = lane & 3;
    int rbase[2];
    rbase[0] = 16 * wm;
    rbase[1] = 240 - 16 * wm;

    // stage q (fp32 row-pair layout; idx 16 = ones pad)
    for (int i = tid; i < CS * DK; i += 512) {
        int r = i >> 4, idx = i & 15;
        int t = r >> 4, rr = r & 15;
        sqp[((t * 8) + (rr & 7)) * 34 + idx * 2 + (rr >> 3)] = f2tf(qg[i] * 0.25f);
    }
    if (tid < 256) {
        int t = tid >> 4, rr = tid & 15;
        sqp[((t * 8) + (rr & 7)) * 34 + 32 + (rr >> 3)] = 1.0f;
        szs[tid] = 0.f;
    }
    // stage k as fp16x2 idx-pairs: slot order (tg, tg+4) interleaved
    for (int i = tid; i < CS * 8; i += 512) {
        int r = i >> 3, t = i & 7;
        float2 kk = *(const float2*)&kg[r * 16 + 2 * t];
        sk2[r * 8 + (t & 3) * 2 + (t >> 2)] = pack2(kk.x, kk.y);
    }
    // stage V as fp16x2 pairs over adjacent chunk-rows
    for (int i = tid; i < 128 * 16; i += 512) {
        int jp = i >> 4, f4 = (i & 15) * 4;
        float4 x0 = *(const float4*)&vg[(2 * jp) * 64 + f4];
        float4 x1 = *(const float4*)&vg[(2 * jp + 1) * 64 + f4];
        sv2[(f4 + 0) * SV2_STRIDE + jp] = pack2(x0.x, x1.x);
        sv2[(f4 + 1) * SV2_STRIDE + jp] = pack2(x0.y, x1.y);
        sv2[(f4 + 2) * SV2_STRIDE + jp] = pack2(x0.z, x1.z);
        sv2[(f4 + 3) * SV2_STRIDE + jp] = pack2(x0.w, x1.w);
    }
    lut_build(spd, spe, sw, spde, tid);
    __syncthreads();

    // Q fragments per mirrored tile: a0..a3 of m16n8k16 (K = full DK=16)
    unsigned qf[2][4];
    #pragma unroll
    for (int mt = 0; mt < 2; mt++) {
        int qbase = (((rbase[mt] >> 4) * 8) + g) * 34;
        float2 t0 = *(float2*)&sqp[qbase + (2 * tg) * 2];
        float2 t1 = *(float2*)&sqp[qbase + (2 * tg + 1) * 2];
        float2 t2 = *(float2*)&sqp[qbase + (8 + 2 * tg) * 2];
        float2 t3 = *(float2*)&sqp[qbase + (9 + 2 * tg) * 2];
        qf[mt][0] = pack2(t0.x, t1.x);   // row r0+g,   idx 2tg..2tg+1
        qf[mt][1] = pack2(t0.y, t1.y);   // row r0+g+8
        qf[mt][2] = pack2(t2.x, t3.x);   // row r0+g,   idx 8+2tg..
        qf[mt][3] = pack2(t2.y, t3.y);
    }

    float c[2][4][4];
    #pragma unroll
    for (int mt = 0; mt < 2; mt++)
        #pragma unroll
        for (int nt = 0; nt < 4; nt++)
            #pragma unroll
            for (int u = 0; u < 4; u++) c[mt][nt][u] = 0.f;

    float zp[2][2];
    zp[0][0] = zp[0][1] = zp[1][0] = zp[1][1] = 0.f;

    // ---- intra: barrier-free; K=16 col-blocks; software-pipelined ----
    #pragma unroll
    for (int mt = 0; mt < 2; mt++) {
        const int R = rbase[mt];
        const int nu = R / 16 + 1;          // 16-col blocks covering [0, R+16)
        const int r0 = R + g;
        // prologue: S-mma for block u=0
        float sf0[4] = {0.f, 0.f, 0.f, 0.f};
        float sf1[4] = {0.f, 0.f, 0.f, 0.f};
        {
            uint2 kb0 = *(uint2*)&sk2[g * 8 + 2 * tg];
            uint2 kb1 = *(uint2*)&sk2[(8 + g) * 8 + 2 * tg];
            mma16(sf0, qf[mt][0], qf[mt][1], qf[mt][2], qf[mt][3],
                  kb0.x, kb0.y);
            mma16(sf1, qf[mt][0], qf[mt][1], qf[mt][2], qf[mt][3],
                  kb1.x, kb1.y);
        }
        for (int u = 0; u < nu; u++) {
            // consume sf -> phi/af (sf dead after this block)
            int jg0 = 16 * u + 2 * tg, jg1 = jg0 + 8;
            float v00 = (r0 >= jg0)     ? fmaf(0.5f * sf0[0], sf0[0], sf0[0] + 1.f) : 0.f;
            float v01 = (r0 >= jg0 + 1) ? fmaf(0.5f * sf0[1], sf0[1], sf0[1] + 1.f) : 0.f;
            float v02 = (r0 + 8 >= jg0)     ? fmaf(0.5f * sf0[2], sf0[2], sf0[2] + 1.f) : 0.f;
            float v03 = (r0 + 8 >= jg0 + 1) ? fmaf(0.5f * sf0[3], sf0[3], sf0[3] + 1.f) : 0.f;
            float v10 = (r0 >= jg1)     ? fmaf(0.5f * sf1[0], sf1[0], sf1[0] + 1.f) : 0.f;
            float v11 = (r0 >= jg1 + 1) ? fmaf(0.5f * sf1[1], sf1[1], sf1[1] + 1.f) : 0.f;
            float v12 = (r0 + 8 >= jg1)     ? fmaf(0.5f * sf1[2], sf1[2], sf1[2] + 1.f) : 0.f;
            float v13 = (r0 + 8 >= jg1 + 1) ? fmaf(0.5f * sf1[3], sf1[3], sf1[3] + 1.f) : 0.f;
            zp[mt][0] += v00 + v01 + v10 + v11;
            zp[mt][1] += v02 + v03 + v12 + v13;
            unsigned af0 = pack2(v00, v01);   // (g,  k 2tg..2tg+1)
            unsigned af1 = pack2(v02, v03);   // (g+8, k 2tg..)
            unsigned af2 = pack2(v10, v11);   // (g,  k 8+2tg..)
            unsigned af3 = pack2(v12, v13);
            // re-issue NEXT block's S-mmas into the (now dead) sf registers,
            // ahead of this block's AV-mmas -> latency hidden
            sf0[0] = sf0[1] = sf0[2] = sf0[3] = 0.f;
            sf1[0] = sf1[1] = sf1[2] = sf1[3] = 0.f;
            if (u + 1 < nu) {                 // warp-uniform guard
                int j0 = 16 * (u + 1) + g;
                uint2 kb0 = *(uint2*)&sk2[j0 * 8 + 2 * tg];
                uint2 kb1 = *(uint2*)&sk2[(j0 + 8) * 8 + 2 * tg];
                mma16(sf0, qf[mt][0], qf[mt][1], qf[mt][2], qf[mt][3],
                      kb0.x, kb0.y);
                mma16(sf1, qf[mt][0], qf[mt][1], qf[mt][2], qf[mt][3],
                      kb1.x, kb1.y);
            }
            // AV-mmas for the current block
            #pragma unroll
            for (int nt = 0; nt < 4; nt++) {
                int fc = 32 * wn + 8 * nt + g;
                unsigned bv0 = sv2[fc * SV2_STRIDE + 8 * u + tg];
                unsigned bv1 = sv2[fc * SV2_STRIDE + 8 * u + tg + 4];
                mma16(c[mt][nt], af0, af1, af2, af3, bv0, bv1);
            }
        }
    }

    // intra z merge: wn==0 warps own their rows exclusively
    if (wn == 0) {
        #pragma unroll
        for (int mt = 0; mt < 2; mt++)
            #pragma unroll
            for (int h = 0; h < 2; h++) {
                float v = zp[mt][h];
                v += __shfl_xor_sync(0xffffffffu, v, 1);
                v += __shfl_xor_sync(0xffffffffu, v, 2);
                if (tg == 0) szs[rbase[mt] + g + 8 * h] += v;
            }
    }
    __syncthreads();   // V reads + szs intra writes complete

    // restage sv2 <- w*state as fp16x2 pairs over adjacent p; swst scalar col
    for (int i = tid; i < 80 * 16; i += 512) {
        int pp = i >> 4, f4 = (i & 15) * 4;
        float w0 = sw[2 * pp], w1 = sw[2 * pp + 1];
        float4 x0 = *(const float4*)&st[(2 * pp) * NW + f4];
        float4 x1 = *(const float4*)&st[(2 * pp + 1) * NW + f4];
        sv2[(f4 + 0) * SV2_STRIDE + pp] = pack2(w0 * x0.x, w1 * x1.x);
        sv2[(f4 + 1) * SV2_STRIDE + pp] = pack2(w0 * x0.y, w1 * x1.y);
        sv2[(f4 + 2) * SV2_STRIDE + pp] = pack2(w0 * x0.z, w1 * x1.z);
        sv2[(f4 + 3) * SV2_STRIDE + pp] = pack2(w0 * x0.w, w1 * x1.w);
    }
    if (tid < NP) swst[tid] = sw[tid] * st[tid * NW + 64];
    __syncthreads();

    // inter z (scalar, thread pairs, packed indices)
    {
        int row = tid >> 1, half = tid & 1;
        int t = row >> 4, rr = row & 15;
        const float* qb = &sqp[((t * 8) + (rr & 7)) * 34 + (rr >> 3)];
        float zi = 0.f;
        int pa = half ? 77 : 0, pb = half ? 153 : 77;
        #pragma unroll 7
        for (int p = pa; p < pb; p++) {
            int de = spde[p];
            zi = fmaf(qb[de & 255] * qb[de >> 8], swst[p], zi);
        }
        zi += __shfl_xor_sync(0xffffffffu, zi, 1);
        if (!half) szs[row] += zi;
    }

    // ---- inter: C[256x64] += A[256x160] @ Bstate[160x64]; 10 K=16 steps ----
    const int colb = 32 * wn;
    #pragma unroll 5
    for (int ks = 0; ks < 10; ks++) {
        int p0 = 16 * ks + 2 * tg;
        int d0 = spd[p0],     e0 = spe[p0];
        int d1 = spd[p0 + 1], e1 = spe[p0 + 1];
        int d2 = spd[p0 + 8], e2 = spe[p0 + 8];
        int d3 = spd[p0 + 9], e3 = spe[p0 + 9];
        unsigned a[2][4];
        #pragma unroll
        for (int mt = 0; mt < 2; mt++) {
            int qbase = (((rbase[mt] >> 4) * 8) + g) * 34;
            float2 pd0 = *(float2*)&sqp[qbase + d0 * 2];
            float2 pe0 = *(float2*)&sqp[qbase + e0 * 2];
            float2 pd1 = *(float2*)&sqp[qbase + d1 * 2];
            float2 pe1 = *(float2*)&sqp[qbase + e1 * 2];
            a[mt][0] = pack2(pd0.x * pe0.x, pd1.x * pe1.x);  // row r0,   p0..p0+1
            a[mt][1] = pack2(pd0.y * pe0.y, pd1.y * pe1.y);  // row r0+8
            float2 pd2 = *(float2*)&sqp[qbase + d2 * 2];
            float2 pe2 = *(float2*)&sqp[qbase + e2 * 2];
            float2 pd3 = *(float2*)&sqp[qbase + d3 * 2];
            float2 pe3 = *(float2*)&sqp[qbase + e3 * 2];
            a[mt][2] = pack2(pd2.x * pe2.x, pd3.x * pe3.x);  // row r0,   p0+8..9
            a[mt][3] = pack2(pd2.y * pe2.y, pd3.y * pe3.y);
        }
        #pragma unroll
        for (int nt = 0; nt < 4; nt++) {
            int fc = colb + 8 * nt + g;
            unsigned b0 = sv2[fc * SV2_STRIDE + 8 * ks + tg];
            unsigned b1 = sv2[fc * SV2_STRIDE + 8 * ks + tg + 4];
            #pragma unroll
            for (int mt = 0; mt < 2; mt++)
                mma16(c[mt][nt], a[mt][0], a[mt][1], a[mt][2], a[mt][3],
                      b0, b1);
        }
    }
    __syncthreads();

    // ---- epilogue: divide by z, store ----
    float* og = out + ((size_t)head * LSEQ + (size_t)ch * CS) * DV;
    #pragma unroll
    for (int mt = 0; mt < 2; mt++) {
        int r0 = rbase[mt] + g;
        float z0 = 1.f / (szs[r0] + 1e-6f);
        float z1 = 1.f / (szs[r0 + 8] + 1e-6f);
        #pragma unroll
        for (int nt = 0; nt < 4; nt++) {
            int f = 32 * wn + 8 * nt + 2 * tg;
            *(float2*)&og[r0 * 64 + f] =
                make_float2(c[mt][nt][0] * z0, c[mt][nt][1] * z0);
            *(float2*)&og[(r0 + 8) * 64 + f] =
                make_float2(c[mt][nt][2] * z1, c[mt][nt][3] * z1);
        }
    }
}

// ---------------------------------------------------------------------------
extern "C" void kernel_launch(void* const* d_in, const int* in_sizes, int n_in,
                              void* d_out, int out_size) {
    const float* q = (const float*)d_in[0];
    const float* k = (const float*)d_in[1];
    const float* v = (const float*)d_in[2];
    float* out = (float*)d_out;

    const int smem1 = (17 * SKB_STRIDE + NW * SV2_STRIDE + 4 * NP) *
                      (int)sizeof(float);
    const int smem3 = (128 * 34 + 256 * 8 + 64 * SV2_STRIDE + 256 + 5 * NP) *
                      (int)sizeof(float);

    cudaFuncSetAttribute(k_build, cudaFuncAttributeMaxDynamicSharedMemorySize, smem1);
    cudaFuncSetAttribute(k_main,  cudaFuncAttributeMaxDynamicSharedMemorySize, smem3);

    k_build<<<dim3(BH, NC), 480, smem1>>>(k, v);
    k_scan<<<dim3(BH, 45), 256>>>();
    k_main<<<dim3(BH, NC), 512, smem3>>>(q, k, v, out);
}

// round 17
// speedup vs baseline: 1.0779x; 1.0779x over previous
#include <cuda_runtime.h>
#include <cstdint>

#define BH   32
#define LSEQ 4096
#define DK   16
#define DV   64
#define CS   256
#define NC   16

// Symmetric-pair state: 136 pair rows (d<=e) + 16 linear rows + 1 ones row,
// padded to 160 rows x 72 cols (64 v-cols + 1 aux-sum col + 7 zero pads).
#define NP   160
#define NW   72
#define ST_STRIDE (NP * NW)   // 11520

#define SKB_STRIDE 264        // k_build k layout stride (== 8 mod 32)
#define SV2_STRIDE 132        // packed-pair B tiles stride (== 4 mod 32)

__device__ float g_state[(size_t)BH * NC * ST_STRIDE];

__device__ __forceinline__ unsigned f2t(float x) {
    unsigned u;
    asm("cvt.rna.tf32.f32 %0, %1;" : "=r"(u) : "f"(x));
    return u;
}
__device__ __forceinline__ float f2tf(float x) { return __uint_as_float(f2t(x)); }

// pack two fp32 -> fp16x2 (lo in low half)
__device__ __forceinline__ unsigned pack2(float lo, float hi) {
    unsigned r;
    asm("cvt.rn.f16x2.f32 %0, %1, %2;" : "=r"(r) : "f"(hi), "f"(lo));
    return r;
}

__device__ __forceinline__ void mma16(float* c, unsigned a0, unsigned a1,
                                      unsigned a2, unsigned a3,
                                      unsigned b0, unsigned b1) {
    asm volatile(
        "mma.sync.aligned.m16n8k16.row.col.f32.f16.f16.f32 "
        "{%0,%1,%2,%3},{%4,%5,%6,%7},{%8,%9},{%0,%1,%2,%3};"
        : "+f"(c[0]), "+f"(c[1]), "+f"(c[2]), "+f"(c[3])
        : "r"(a0), "r"(a1), "r"(a2), "r"(a3), "r"(b0), "r"(b1));
}

// p -> (d, e, w). d,e in [0,16]; index 16 hits the pad slot (=1.0f).
// spde packs (2d | 2e<<8) for the z-scalar loop over the sqp layout.
__device__ __forceinline__ void lut_build(int* spd, int* spe, float* sw,
                                          int* spde, int tid) {
    if (tid < NP) {
        int p = tid, d = 0, e;
        float w;
        if (p < 136) {
            int base = 0;
            while (base + (16 - d) <= p) { base += 16 - d; d++; }
            e = d + (p - base);
            w = (d == e) ? 0.5f : 1.0f;
        } else if (p < 152) { d = p - 136; e = 16; w = 1.f; }
        else if (p == 152) { d = 16; e = 16; w = 1.f; }
        else               { d = 16; e = 16; w = 0.f; }
        spd[p] = d; spe[p] = e; sw[p] = w;
        spde[p] = (2 * d) | ((2 * e) << 8);
    }
}

// ---------------------------------------------------------------------------
// Kernel 1: state build = single GEMM  st[160x72] = A[160x256] @ B[256x72]
// fp16 m16n8k16; A built in registers from skb (fp32, c-adjacent pairs);
// B = V+aux staged as fp16x2 pairs over adjacent c. 480 threads, 2 CTAs/SM.
// (Unchanged from the 123.4us baseline.)
// ---------------------------------------------------------------------------
__global__ __launch_bounds__(480, 2)
void k_build(const float* __restrict__ kin, const float* __restrict__ vin) {
    const int head = blockIdx.x, ch = blockIdx.y;
    extern __shared__ float sm[];
    float* skb = sm;                         // [17][SKB_STRIDE] fp32 k (+ones)
    unsigned* sBu = (unsigned*)(skb + 17 * SKB_STRIDE);  // [72][SV2_STRIDE]
    int*   spd = (int*)(sBu + NW * SV2_STRIDE);
    int*   spe = spd + NP;
    float* sw  = (float*)(spe + NP);
    int*   spde = (int*)(sw + NP);

    const float* kg = kin + ((size_t)head * LSEQ + (size_t)ch * CS) * DK;
    const float* vg = vin + ((size_t)head * LSEQ + (size_t)ch * CS) * DV;
    float* st = g_state + (size_t)(head * NC + ch) * ST_STRIDE;

    const int tid = threadIdx.x, warp = tid >> 5, lane = tid & 31;
    const int wm = warp / 3, wn = warp % 3, g = lane >> 2, tg = lane & 3;
    const int rb = 32 * wm, cb = 24 * wn;

    // stage k: skb[idx][c] fp32, idx 16 = ones
    for (int i = tid; i < CS * DK; i += 480) {
        int cc = i >> 4, idx = i & 15;
        skb[idx * SKB_STRIDE + cc] = kg[i];
    }
    for (int i = tid; i < CS; i += 480) skb[16 * SKB_STRIDE + i] = 1.0f;
    // stage B: half2 pairs over (c=2cp, 2cp+1); cols 0..63 = V, 64 = ones
    for (int i = tid; i < 128 * 18; i += 480) {
        int cp = i / 18, fg = i - cp * 18, f4 = fg * 4;
        if (f4 < 64) {
            float4 x0 = *(const float4*)&vg[(2 * cp) * 64 + f4];
            float4 x1 = *(const float4*)&vg[(2 * cp + 1) * 64 + f4];
            sBu[(f4 + 0) * SV2_STRIDE + cp] = pack2(x0.x, x1.x);
            sBu[(f4 + 1) * SV2_STRIDE + cp] = pack2(x0.y, x1.y);
            sBu[(f4 + 2) * SV2_STRIDE + cp] = pack2(x0.z, x1.z);
            sBu[(f4 + 3) * SV2_STRIDE + cp] = pack2(x0.w, x1.w);
        } else {
            #pragma unroll
            for (int u = 0; u < 4; u++) {
                int f = f4 + u;
                sBu[f * SV2_STRIDE + cp] = (f == 64) ? 0x3C003C00u : 0u;
            }
        }
    }
    lut_build(spd, spe, sw, spde, tid);
    __syncthreads();

    int rd[2][2], re[2][2];
    #pragma unroll
    for (int mt = 0; mt < 2; mt++) {
        int r0 = rb + 16 * mt + g;
        rd[mt][0] = spd[r0];     re[mt][0] = spe[r0];
        rd[mt][1] = spd[r0 + 8]; re[mt][1] = spe[r0 + 8];
    }

    float c[2][3][4];
    #pragma unroll
    for (int mt = 0; mt < 2; mt++)
        #pragma unroll
        for (int nt = 0; nt < 3; nt++)
            #pragma unroll
            for (int u = 0; u < 4; u++) c[mt][nt][u] = 0.f;

    #pragma unroll 4
    for (int ks = 0; ks < 16; ks++) {
        const int c0 = 16 * ks + 2 * tg;
        unsigned a[2][4];
        #pragma unroll
        for (int mt = 0; mt < 2; mt++) {
            float2 pd0 = *(float2*)&skb[rd[mt][0] * SKB_STRIDE + c0];
            float2 pe0 = *(float2*)&skb[re[mt][0] * SKB_STRIDE + c0];
            float2 pd1 = *(float2*)&skb[rd[mt][1] * SKB_STRIDE + c0];
            float2 pe1 = *(float2*)&skb[re[mt][1] * SKB_STRIDE + c0];
            a[mt][0] = pack2(pd0.x * pe0.x, pd0.y * pe0.y);  // row r0, c0..c0+1
            a[mt][1] = pack2(pd1.x * pe1.x, pd1.y * pe1.y);  // row r0+8
            float2 qd0 = *(float2*)&skb[rd[mt][0] * SKB_STRIDE + c0 + 8];
            float2 qe0 = *(float2*)&skb[re[mt][0] * SKB_STRIDE + c0 + 8];
            float2 qd1 = *(float2*)&skb[rd[mt][1] * SKB_STRIDE + c0 + 8];
            float2 qe1 = *(float2*)&skb[re[mt][1] * SKB_STRIDE + c0 + 8];
            a[mt][2] = pack2(qd0.x * qe0.x, qd0.y * qe0.y);  // row r0, c0+8..9
            a[mt][3] = pack2(qd1.x * qe1.x, qd1.y * qe1.y);
        }
        #pragma unroll
        for (int nt = 0; nt < 3; nt++) {
            int fc = cb + 8 * nt + g;
            unsigned b0 = sBu[fc * SV2_STRIDE + 8 * ks + tg];
            unsigned b1 = sBu[fc * SV2_STRIDE + 8 * ks + tg + 4];
            #pragma unroll
            for (int mt = 0; mt < 2; mt++)
                mma16(c[mt][nt], a[mt][0], a[mt][1], a[mt][2], a[mt][3],
                      b0, b1);
        }
    }

    #pragma unroll
    for (int mt = 0; mt < 2; mt++)
        #pragma unroll
        for (int nt = 0; nt < 3; nt++) {
            int r0 = rb + 16 * mt + g, col = cb + 8 * nt + 2 * tg;
            *(float2*)&st[r0 * NW + col] =
                make_float2(c[mt][nt][0], c[mt][nt][1]);
            *(float2*)&st[(r0 + 8) * NW + col] =
                make_float2(c[mt][nt][2], c[mt][nt][3]);
        }
}

// ---------------------------------------------------------------------------
// Kernel 2: exclusive prefix scan over chunk axis. One element per thread.
// ---------------------------------------------------------------------------
__global__ void k_scan() {
    float* base = g_state + (size_t)blockIdx.x * NC * ST_STRIDE +
                  blockIdx.y * blockDim.x + threadIdx.x;
    float v[NC];
    #pragma unroll
    for (int c = 0; c < NC; c++) v[c] = base[(size_t)c * ST_STRIDE];
    float run = 0.f;
    #pragma unroll
    for (int c = 0; c < NC; c++) {
        float t = v[c];
        v[c] = run;
        run += t;
    }
    #pragma unroll
    for (int c = 0; c < NC; c++) base[(size_t)c * ST_STRIDE] = v[c];
}

// ---------------------------------------------------------------------------
// Kernel 3: output. 256 threads (8 warps), 2 CTAs/SM. Each warp owns M=32
// (mirrored tiles) x FULL N=64 — the wn duplication of S-mma/phi (intra) and
// A-fragment build (inter) is eliminated; AV/inter mma totals unchanged.
// ---------------------------------------------------------------------------
__global__ __launch_bounds__(256, 2)
void k_main(const float* __restrict__ qin, const float* __restrict__ kin,
            const float* __restrict__ vin, float* __restrict__ out) {
    const int head = blockIdx.x, ch = blockIdx.y;
    extern __shared__ float sm[];
    float* sqp = sm;                           // [128][34] fp32 q (row pairs)
    unsigned* sk2 = (unsigned*)(sqp + 128 * 34);      // [256][8] fp16x2 k
    unsigned* sv2 = sk2 + 256 * 8;                    // [64][SV2_STRIDE]
    float* szs = (float*)(sv2 + 64 * SV2_STRIDE);     // [256]
    int*   spd = (int*)(szs + 256);
    int*   spe = spd + NP;
    float* sw  = (float*)(spe + NP);
    int*   spde = (int*)(sw + NP);
    float* swst = (float*)(spde + NP);         // [160] w*state[:,64]

    const float* qg = qin + ((size_t)head * LSEQ + (size_t)ch * CS) * DK;
    const float* kg = kin + ((size_t)head * LSEQ + (size_t)ch * CS) * DK;
    const float* vg = vin + ((size_t)head * LSEQ + (size_t)ch * CS) * DV;
    const float* st = g_state + (size_t)(head * NC + ch) * ST_STRIDE;

    const int tid = threadIdx.x, warp = tid >> 5, lane = tid & 31;
    const int wm = warp, g = lane >> 2, tg = lane & 3;
    int rbase[2];
    rbase[0] = 16 * wm;
    rbase[1] = 240 - 16 * wm;

    // stage q (fp32 row-pair layout; idx 16 = ones pad)
    for (int i = tid; i < CS * DK; i += 256) {
        int r = i >> 4, idx = i & 15;
        int t = r >> 4, rr = r & 15;
        sqp[((t * 8) + (rr & 7)) * 34 + idx * 2 + (rr >> 3)] = f2tf(qg[i] * 0.25f);
    }
    {
        int t = tid >> 4, rr = tid & 15;
        sqp[((t * 8) + (rr & 7)) * 34 + 32 + (rr >> 3)] = 1.0f;
        szs[tid] = 0.f;
    }
    // stage k as fp16x2 idx-pairs: slot order (tg, tg+4) interleaved
    for (int i = tid; i < CS * 8; i += 256) {
        int r = i >> 3, t = i & 7;
        float2 kk = *(const float2*)&kg[r * 16 + 2 * t];
        sk2[r * 8 + (t & 3) * 2 + (t >> 2)] = pack2(kk.x, kk.y);
    }
    // stage V as fp16x2 pairs over adjacent chunk-rows
    for (int i = tid; i < 128 * 16; i += 256) {
        int jp = i >> 4, f4 = (i & 15) * 4;
        float4 x0 = *(const float4*)&vg[(2 * jp) * 64 + f4];
        float4 x1 = *(const float4*)&vg[(2 * jp + 1) * 64 + f4];
        sv2[(f4 + 0) * SV2_STRIDE + jp] = pack2(x0.x, x1.x);
        sv2[(f4 + 1) * SV2_STRIDE + jp] = pack2(x0.y, x1.y);
        sv2[(f4 + 2) * SV2_STRIDE + jp] = pack2(x0.z, x1.z);
        sv2[(f4 + 3) * SV2_STRIDE + jp] = pack2(x0.w, x1.w);
    }
    lut_build(spd, spe, sw, spde, tid);
    __syncthreads();

    // Q fragments per mirrored tile: a0..a3 of m16n8k16 (K = full DK=16)
    unsigned qf[2][4];
    #pragma unroll
    for (int mt = 0; mt < 2; mt++) {
        int qbase = (((rbase[mt] >> 4) * 8) + g) * 34;
        float2 t0 = *(float2*)&sqp[qbase + (2 * tg) * 2];
        float2 t1 = *(float2*)&sqp[qbase + (2 * tg + 1) * 2];
        float2 t2 = *(float2*)&sqp[qbase + (8 + 2 * tg) * 2];
        float2 t3 = *(float2*)&sqp[qbase + (9 + 2 * tg) * 2];
        qf[mt][0] = pack2(t0.x, t1.x);   // row r0+g,   idx 2tg..2tg+1
        qf[mt][1] = pack2(t0.y, t1.y);   // row r0+g+8
        qf[mt][2] = pack2(t2.x, t3.x);   // row r0+g,   idx 8+2tg..
        qf[mt][3] = pack2(t2.y, t3.y);
    }

    float c[2][8][4];
    #pragma unroll
    for (int mt = 0; mt < 2; mt++)
        #pragma unroll
        for (int nt = 0; nt < 8; nt++)
            #pragma unroll
            for (int u = 0; u < 4; u++) c[mt][nt][u] = 0.f;

    float zp[2][2];
    zp[0][0] = zp[0][1] = zp[1][0] = zp[1][1] = 0.f;

    // ---- intra: barrier-free; K=16 col-blocks; full N per warp ----
    #pragma unroll
    for (int mt = 0; mt < 2; mt++) {
        const int R = rbase[mt];
        const int nu = R / 16 + 1;          // 16-col blocks covering [0, R+16)
        const int r0 = R + g;
        for (int u = 0; u < nu; u++) {
            int j0 = 16 * u + g;
            uint2 kb0 = *(uint2*)&sk2[j0 * 8 + 2 * tg];          // block J0
            uint2 kb1 = *(uint2*)&sk2[(j0 + 8) * 8 + 2 * tg];    // block J1
            float sf0[4] = {0.f, 0.f, 0.f, 0.f};
            float sf1[4] = {0.f, 0.f, 0.f, 0.f};
            mma16(sf0, qf[mt][0], qf[mt][1], qf[mt][2], qf[mt][3],
                  kb0.x, kb0.y);
            mma16(sf1, qf[mt][0], qf[mt][1], qf[mt][2], qf[mt][3],
                  kb1.x, kb1.y);
            int jg0 = 16 * u + 2 * tg, jg1 = jg0 + 8;
            float v00 = (r0 >= jg0)     ? fmaf(0.5f * sf0[0], sf0[0], sf0[0] + 1.f) : 0.f;
            float v01 = (r0 >= jg0 + 1) ? fmaf(0.5f * sf0[1], sf0[1], sf0[1] + 1.f) : 0.f;
            float v02 = (r0 + 8 >= jg0)     ? fmaf(0.5f * sf0[2], sf0[2], sf0[2] + 1.f) : 0.f;
            float v03 = (r0 + 8 >= jg0 + 1) ? fmaf(0.5f * sf0[3], sf0[3], sf0[3] + 1.f) : 0.f;
            float v10 = (r0 >= jg1)     ? fmaf(0.5f * sf1[0], sf1[0], sf1[0] + 1.f) : 0.f;
            float v11 = (r0 >= jg1 + 1) ? fmaf(0.5f * sf1[1], sf1[1], sf1[1] + 1.f) : 0.f;
            float v12 = (r0 + 8 >= jg1)     ? fmaf(0.5f * sf1[2], sf1[2], sf1[2] + 1.f) : 0.f;
            float v13 = (r0 + 8 >= jg1 + 1) ? fmaf(0.5f * sf1[3], sf1[3], sf1[3] + 1.f) : 0.f;
            zp[mt][0] += v00 + v01 + v10 + v11;
            zp[mt][1] += v02 + v03 + v12 + v13;
            unsigned af0 = pack2(v00, v01);   // (g,  k 2tg..2tg+1)
            unsigned af1 = pack2(v02, v03);   // (g+8, k 2tg..)
            unsigned af2 = pack2(v10, v11);   // (g,  k 8+2tg..)
            unsigned af3 = pack2(v12, v13);
            #pragma unroll
            for (int nt = 0; nt < 8; nt++) {
                int fc = 8 * nt + g;
                unsigned bv0 = sv2[fc * SV2_STRIDE + 8 * u + tg];
                unsigned bv1 = sv2[fc * SV2_STRIDE + 8 * u + tg + 4];
                mma16(c[mt][nt], af0, af1, af2, af3, bv0, bv1);
            }
        }
    }

    // intra z merge: each warp owns its rows exclusively
    #pragma unroll
    for (int mt = 0; mt < 2; mt++)
        #pragma unroll
        for (int h = 0; h < 2; h++) {
            float v = zp[mt][h];
            v += __shfl_xor_sync(0xffffffffu, v, 1);
            v += __shfl_xor_sync(0xffffffffu, v, 2);
            if (tg == 0) szs[rbase[mt] + g + 8 * h] += v;
        }
    __syncthreads();   // V reads + szs intra writes complete

    // restage sv2 <- w*state as fp16x2 pairs over adjacent p; swst scalar col
    for (int i = tid; i < 80 * 16; i += 256) {
        int pp = i >> 4, f4 = (i & 15) * 4;
        float w0 = sw[2 * pp], w1 = sw[2 * pp + 1];
        float4 x0 = *(const float4*)&st[(2 * pp) * NW + f4];
        float4 x1 = *(const float4*)&st[(2 * pp + 1) * NW + f4];
        sv2[(f4 + 0) * SV2_STRIDE + pp] = pack2(w0 * x0.x, w1 * x1.x);
        sv2[(f4 + 1) * SV2_STRIDE + pp] = pack2(w0 * x0.y, w1 * x1.y);
        sv2[(f4 + 2) * SV2_STRIDE + pp] = pack2(w0 * x0.z, w1 * x1.z);
        sv2[(f4 + 3) * SV2_STRIDE + pp] = pack2(w0 * x0.w, w1 * x1.w);
    }
    if (tid < NP) swst[tid] = sw[tid] * st[tid * NW + 64];
    __syncthreads();

    // inter z (scalar, one row per thread, packed indices)
    {
        int row = tid;
        int t = row >> 4, rr = row & 15;
        const float* qb = &sqp[((t * 8) + (rr & 7)) * 34 + (rr >> 3)];
        float zi = 0.f;
        #pragma unroll 9
        for (int p = 0; p < 153; p++) {
            int de = spde[p];
            zi = fmaf(qb[de & 255] * qb[de >> 8], swst[p], zi);
        }
        szs[row] += zi;
    }

    // ---- inter: C[256x64] += A[256x160] @ Bstate[160x64]; 10 K=16 steps ----
    #pragma unroll 5
    for (int ks = 0; ks < 10; ks++) {
        int p0 = 16 * ks + 2 * tg;
        int d0 = spd[p0],     e0 = spe[p0];
        int d1 = spd[p0 + 1], e1 = spe[p0 + 1];
        int d2 = spd[p0 + 8], e2 = spe[p0 + 8];
        int d3 = spd[p0 + 9], e3 = spe[p0 + 9];
        unsigned a[2][4];
        #pragma unroll
        for (int mt = 0; mt < 2; mt++) {
            int qbase = (((rbase[mt] >> 4) * 8) + g) * 34;
            float2 pd0 = *(float2*)&sqp[qbase + d0 * 2];
            float2 pe0 = *(float2*)&sqp[qbase + e0 * 2];
            float2 pd1 = *(float2*)&sqp[qbase + d1 * 2];
            float2 pe1 = *(float2*)&sqp[qbase + e1 * 2];
            a[mt][0] = pack2(pd0.x * pe0.x, pd1.x * pe1.x);  // row r0,   p0..p0+1
            a[mt][1] = pack2(pd0.y * pe0.y, pd1.y * pe1.y);  // row r0+8
            float2 pd2 = *(float2*)&sqp[qbase + d2 * 2];
            float2 pe2 = *(float2*)&sqp[qbase + e2 * 2];
            float2 pd3 = *(float2*)&sqp[qbase + d3 * 2];
            float2 pe3 = *(float2*)&sqp[qbase + e3 * 2];
            a[mt][2] = pack2(pd2.x * pe2.x, pd3.x * pe3.x);  // row r0,   p0+8..9
            a[mt][3] = pack2(pd2.y * pe2.y, pd3.y * pe3.y);
        }
        #pragma unroll
        for (int nt = 0; nt < 8; nt++) {
            int fc = 8 * nt + g;
            unsigned b0 = sv2[fc * SV2_STRIDE + 8 * ks + tg];
            unsigned b1 = sv2[fc * SV2_STRIDE + 8 * ks + tg + 4];
            #pragma unroll
            for (int mt = 0; mt < 2; mt++)
                mma16(c[mt][nt], a[mt][0], a[mt][1], a[mt][2], a[mt][3],
                      b0, b1);
        }
    }
    __syncthreads();

    // ---- epilogue: divide by z, store ----
    float* og = out + ((size_t)head * LSEQ + (size_t)ch * CS) * DV;
    #pragma unroll
    for (int mt = 0; mt < 2; mt++) {
        int r0 = rbase[mt] + g;
        float z0 = 1.f / (szs[r0] + 1e-6f);
        float z1 = 1.f / (szs[r0 + 8] + 1e-6f);
        #pragma unroll
        for (int nt = 0; nt < 8; nt++) {
            int f = 8 * nt + 2 * tg;
            *(float2*)&og[r0 * 64 + f] =
                make_float2(c[mt][nt][0] * z0, c[mt][nt][1] * z0);
            *(float2*)&og[(r0 + 8) * 64 + f] =
                make_float2(c[mt][nt][2] * z1, c[mt][nt][3] * z1);
        }
    }
}

// ---------------------------------------------------------------------------
extern "C" void kernel_launch(void* const* d_in, const int* in_sizes, int n_in,
                              void* d_out, int out_size) {
    const float* q = (const float*)d_in[0];
    const float* k = (const float*)d_in[1];
    const float* v = (const float*)d_in[2];
    float* out = (float*)d_out;

    const int smem1 = (17 * SKB_STRIDE + NW * SV2_STRIDE + 4 * NP) *
                      (int)sizeof(float);
    const int smem3 = (128 * 34 + 256 * 8 + 64 * SV2_STRIDE + 256 + 5 * NP) *
                      (int)sizeof(float);

    cudaFuncSetAttribute(k_build, cudaFuncAttributeMaxDynamicSharedMemorySize, smem1);
    cudaFuncSetAttribute(k_main,  cudaFuncAttributeMaxDynamicSharedMemorySize, smem3);

    k_build<<<dim3(BH, NC), 480, smem1>>>(k, v);
    k_scan<<<dim3(BH, 45), 256>>>();
    k_main<<<dim3(BH, NC), 256, smem3>>>(q, k, v, out);
}